// round 15
// baseline (speedup 1.0000x reference)
#include <cuda_runtime.h>

// NCDE decoder: B=4096, 255 RK4 steps, C=16, H=128, O=4.
// Kernel 0 (prep): per (b,t) record = 3 x (-2*xdot) tables (48f) + 3 channel
//   sums + pad -> 52 floats, streamed from coeffs (memory-bound).
// Kernel 1 (scan): one 128-thread block per TWO batch elements; records
//   cp.async-prefetched (triple buffer) 2 steps ahead; 4 barriers per
//   2-batch-step; quad-reciprocal tanh; fma.rn.f32x2 packed args.
// Kernel 2 (proj): shfl-free smem-tiled out = z_all @ W_out + b_out.

#define Hh 128
#define Cc 16
#define NSTEP 255
#define RPITCH 52                    // record floats (16B-aligned: 208B)
#define BUFSTRIDE 416u               // 2*RPITCH*4 bytes between tb buffers
#define L2E2 2.8853900817779268f     // 2*log2(e), folded into W2/b2

typedef unsigned long long ull;

__device__ float zscr[4096 * 256 * 128];          // 512 MB z trajectory
__device__ float tblg[4096 * 255 * RPITCH];       // 217 MB xdot records

__device__ __forceinline__ ull pack2(float lo, float hi) {
    ull r; asm("mov.b64 %0, {%1, %2};" : "=l"(r) : "f"(lo), "f"(hi)); return r;
}
__device__ __forceinline__ void unpack2(ull v, float& lo, float& hi) {
    asm("mov.b64 {%0, %1}, %2;" : "=f"(lo), "=f"(hi) : "l"(v));
}
__device__ __forceinline__ ull fma2(ull a, ull b, ull c) {
    ull d; asm("fma.rn.f32x2 %0, %1, %2, %3;" : "=l"(d) : "l"(a), "l"(b), "l"(c)); return d;
}
__device__ __forceinline__ float ex2f(float x) {
    float e; asm("ex2.approx.f32 %0, %1;" : "=f"(e) : "f"(x)); return e;
}
__device__ __forceinline__ float rcpf(float x) {
    float r; asm("rcp.approx.f32 %0, %1;" : "=f"(r) : "f"(x)); return r;
}
__device__ __forceinline__ unsigned smem_u32(const void* p) {
    return (unsigned)__cvta_generic_to_shared(p);
}
#define CP16(dst, src) \
    asm volatile("cp.async.ca.shared.global [%0], [%1], 16;" :: "r"(dst), "l"(src) : "memory")
#define CP_COMMIT() asm volatile("cp.async.commit_group;" ::: "memory")
#define CP_WAIT1()  asm volatile("cp.async.wait_group 1;" ::: "memory")

__device__ __forceinline__ void redsum2(float& a, float& b) {
#pragma unroll
    for (int off = 16; off; off >>= 1) {
        a += __shfl_xor_sync(0xffffffffu, a, off);
        b += __shfl_xor_sync(0xffffffffu, b, off);
    }
}
__device__ __forceinline__ void redsum4(float& a, float& b, float& c, float& d) {
#pragma unroll
    for (int off = 16; off; off >>= 1) {
        a += __shfl_xor_sync(0xffffffffu, a, off);
        b += __shfl_xor_sync(0xffffffffu, b, off);
        c += __shfl_xor_sync(0xffffffffu, c, off);
        d += __shfl_xor_sync(0xffffffffu, d, off);
    }
}

// ---------------- kernel 0: record prepass (memory-bound) ----------------
__global__ __launch_bounds__(256) void prep_kernel(const float* __restrict__ coeffs)
{
    const int idx = blockIdx.x * 256 + threadIdx.x;     // = b*255 + t
    if (idx >= 4096 * 255) return;
    const float4* src = (const float4*)(coeffs + (size_t)idx * 64 + 16);
    float4* r4 = (float4*)(tblg + (size_t)idx * RPITCH);

    float S0 = 0.f, SC = 0.f, SD = 0.f;
#pragma unroll
    for (int i = 0; i < 4; i++) {
        const float4 sb = src[i], sc = src[4 + i], sd = src[8 + i];
        float4 x0, xh, x1;
        x0.x = -2.f * sb.x;  x0.y = -2.f * sb.y;  x0.z = -2.f * sb.z;  x0.w = -2.f * sb.w;
        xh.x = -2.f * fmaf(0.25f, sd.x, fmaf(0.5f, sc.x, sb.x));
        xh.y = -2.f * fmaf(0.25f, sd.y, fmaf(0.5f, sc.y, sb.y));
        xh.z = -2.f * fmaf(0.25f, sd.z, fmaf(0.5f, sc.z, sb.z));
        xh.w = -2.f * fmaf(0.25f, sd.w, fmaf(0.5f, sc.w, sb.w));
        x1.x = -2.f * ((sb.x + sc.x) + sd.x);
        x1.y = -2.f * ((sb.y + sc.y) + sd.y);
        x1.z = -2.f * ((sb.z + sc.z) + sd.z);
        x1.w = -2.f * ((sb.w + sc.w) + sd.w);
        r4[i] = x0; r4[4 + i] = xh; r4[8 + i] = x1;
        S0 += (sb.x + sb.y) + (sb.z + sb.w);
        SC += (sc.x + sc.y) + (sc.z + sc.w);
        SD += (sd.x + sd.y) + (sd.z + sd.w);
    }
    r4[12] = make_float4(S0, fmaf(0.25f, SD, fmaf(0.5f, SC, S0)), (S0 + SC) + SD, 0.f);
}

// One stage's vf partial for one batch: q_h = sum_c tanh(args)*xdot_c.
__device__ __forceinline__ float stage_q(
    const ull H0, const ull H1,
    const ull* __restrict__ wa, const ull* __restrict__ wbp,
    const ull* __restrict__ b2p, const float* __restrict__ xd)
{
    float qa = 0.f, qb = 0.f;
#pragma unroll
    for (int qi = 0; qi < 4; qi++) {
        ull y0 = fma2(H0, wa[2 * qi],     fma2(H1, wbp[2 * qi],     b2p[2 * qi]));
        ull y1 = fma2(H0, wa[2 * qi + 1], fma2(H1, wbp[2 * qi + 1], b2p[2 * qi + 1]));
        float ya, yb, yc, yd;
        unpack2(y0, ya, yb); unpack2(y1, yc, yd);
        const float t0 = ex2f(fminf(ya, 30.f)) + 1.f;
        const float t1 = ex2f(fminf(yb, 30.f)) + 1.f;
        const float t2 = ex2f(fminf(yc, 30.f)) + 1.f;
        const float t3 = ex2f(fminf(yd, 30.f)) + 1.f;
        const float4 x4 = *(const float4*)&xd[4 * qi];
        const float P0 = t0 * t1;
        const float N0 = fmaf(x4.y, t0, x4.x * t1);
        const float P1 = t2 * t3;
        const float N1 = fmaf(x4.w, t2, x4.z * t3);
        const float R  = rcpf(P0 * P1);
        const float N  = fmaf(N1, P0, N0 * P1);
        if (qi & 1) qb = fmaf(R, N, qb); else qa = fmaf(R, N, qa);
    }
    return qa + qb;
}

// ---------------- kernel 1: RK4 scan, two batches per block ----------------
__global__ __launch_bounds__(128, 4) void ncde_kernel(
    const float* __restrict__ coeffs,   // (B, 255, 64)
    const float* __restrict__ W_init,   // (16, 128)
    const float* __restrict__ b_init,   // (128)
    const float* __restrict__ W1,       // (128, 2)
    const float* __restrict__ b1,       // (2)
    const float* __restrict__ W2,       // (2, 2048)
    const float* __restrict__ b2)       // (2048)
{
    const int h    = threadIdx.x;
    const int lane = h & 31;
    const int warp = h >> 5;

    __shared__ __align__(16) float tb[3][2][RPITCH];   // record triple buffer
    __shared__ __align__(16) float sred[2][16];        // [phase][warp*4 + j]
    __shared__ float sa0[2][Cc];

    // cp.async source/dest for this thread (threads h<26: 13 float4 x 2 batches)
    const int cpbat = h / 13, cpj = h - cpbat * 13;    // valid for h<26
    const float* gpre = tblg + ((size_t)(blockIdx.x * 2 + (cpbat & 1)) * NSTEP) * RPITCH + cpj * 4;
    const unsigned sdst0 = smem_u32(&tb[0][cpbat & 1][cpj * 4]);

    // prologue prefetch: records t=0 -> tb[0], t=1 -> tb[1]
    if (h < 26) CP16(sdst0, gpre);
    CP_COMMIT();
    if (h < 26) CP16(sdst0 + BUFSTRIDE, gpre + RPITCH);
    CP_COMMIT();

    // ---- per-thread packed weight slices (arg scale 2*log2e pre-folded) ----
    ull wa[8], wbp[8], b2p[8];
#pragma unroll
    for (int p = 0; p < 8; p++) {
        wa[p]  = pack2(W2[h * Cc + 2 * p] * L2E2,           W2[h * Cc + 2 * p + 1] * L2E2);
        wbp[p] = pack2(W2[Hh * Cc + h * Cc + 2 * p] * L2E2, W2[Hh * Cc + h * Cc + 2 * p + 1] * L2E2);
        b2p[p] = pack2(b2[h * Cc + 2 * p] * L2E2,           b2[h * Cc + 2 * p + 1] * L2E2);
    }
    const float w1a = W1[h * 2 + 0], w1b = W1[h * 2 + 1];
    const float b10 = b1[0], b11 = b1[1];

    const float* crowA = coeffs + (size_t)(blockIdx.x * 2 + 0) * (NSTEP * 64);
    const float* crowB = coeffs + (size_t)(blockIdx.x * 2 + 1) * (NSTEP * 64);
    float* zrowA = zscr + (size_t)(blockIdx.x * 2 + 0) * (256 * Hh) + h;
    float* zrowB = zscr + (size_t)(blockIdx.x * 2 + 1) * (256 * Hh) + h;

    if (h < Cc) { sa0[0][h] = crowA[h]; sa0[1][h] = crowB[h]; }

    // SW1 = column sums of W1 (k = S + q decomposition)
    {
        float r0 = w1a, r1 = w1b;
        redsum2(r0, r1);
        if (lane == 0) { sred[0][warp * 4] = r0; sred[0][warp * 4 + 1] = r1; }
    }
    __syncthreads();
    const float SW1a = sred[0][0] + sred[0][4] + sred[0][8]  + sred[0][12];
    const float SW1b = sred[0][1] + sred[0][5] + sred[0][9]  + sred[0][13];

    // z0 = X0 @ W_init + b_init, both batches
    float zA = b_init[h], zB = zA;
#pragma unroll
    for (int c = 0; c < Cc; c++) {
        const float wi = W_init[c * Hh + h];
        zA = fmaf(sa0[0][c], wi, zA);
        zB = fmaf(sa0[1][c], wi, zB);
    }
    zrowA[0] = zA;
    zrowB[0] = zB;

    // uz for both batches; wait for record 0 under the same barrier
    float uzA0, uzA1, uzB0, uzB1;
    {
        float r0 = zA * w1a, r1 = zA * w1b, r2 = zB * w1a, r3 = zB * w1b;
        redsum4(r0, r1, r2, r3);
        if (lane == 0) {
            *(float4*)&sred[1][warp * 4] = make_float4(r0, r1, r2, r3);
        }
        CP_WAIT1();                 // record 0 landed
        __syncthreads();
        const float4 f0 = *(const float4*)&sred[1][0];
        const float4 f1 = *(const float4*)&sred[1][4];
        const float4 f2 = *(const float4*)&sred[1][8];
        const float4 f3 = *(const float4*)&sred[1][12];
        uzA0 = f0.x + f1.x + f2.x + f3.x;
        uzA1 = f0.y + f1.y + f2.y + f3.y;
        uzB0 = f0.z + f1.z + f2.z + f3.z;
        uzB1 = f0.w + f1.w + f2.w + f3.w;
    }

    const float* gnext = gpre + 2 * RPITCH;   // record t+2 source (h<26)
    int buf = 0;                               // tb[buf] holds record t
    int ph = 0;

    for (int t = 0; t < NSTEP; t++) {
        const int pf = (buf == 0) ? 2 : buf - 1;   // (buf+2)%3

        // S scalars for this step (broadcast LDS; published by prev barrier)
        const float SA0 = tb[buf][0][48], SAh = tb[buf][0][49], SA1 = tb[buf][0][50];
        const float SB0 = tb[buf][1][48], SBh = tb[buf][1][49], SB1 = tb[buf][1][50];

        // prefetch record t+2 into tb[pf] (its last reader was step t-1)
        if (h < 26 && t < NSTEP - 2) CP16(sdst0 + (unsigned)pf * BUFSTRIDE, gnext);
        CP_COMMIT();

        float ukA0 = 0.f, ukA1 = 0.f, sA0 = 0.f, sA1 = 0.f, ksumA = 0.f;
        float ukB0 = 0.f, ukB1 = 0.f, sB0 = 0.f, sB1 = 0.f, ksumB = 0.f;

#pragma unroll
        for (int st = 0; st < 4; st++) {
            const float alpha = (st == 0) ? 0.f : (st == 3) ? 1.f : 0.5f;
            const int   xi    = (st == 0) ? 0   : (st == 3) ? 2   : 1;
            const float wgt   = (st == 0 || st == 3) ? 1.f : 2.f;
            const float SstA  = (st == 0) ? SA0 : (st == 3) ? SA1 : SAh;
            const float SstB  = (st == 0) ? SB0 : (st == 3) ? SB1 : SBh;

            // A quad, then A's shfl chain issues while B's quad computes
            const float hA0 = fmaxf(fmaf(alpha, ukA0, uzA0) + b10, 0.f);
            const float hA1 = fmaxf(fmaf(alpha, ukA1, uzA1) + b11, 0.f);
            float rA0, rA1;
            {
                const float qA = stage_q(pack2(hA0, hA0), pack2(hA1, hA1),
                                         wa, wbp, b2p, &tb[buf][0][xi * 16]);
                rA0 = qA * w1a; rA1 = qA * w1b;
                ksumA = fmaf(wgt, SstA + qA, ksumA);
            }
            redsum2(rA0, rA1);

            const float hB0 = fmaxf(fmaf(alpha, ukB0, uzB0) + b10, 0.f);
            const float hB1 = fmaxf(fmaf(alpha, ukB1, uzB1) + b11, 0.f);
            float rB0, rB1;
            {
                const float qB = stage_q(pack2(hB0, hB0), pack2(hB1, hB1),
                                         wa, wbp, b2p, &tb[buf][1][xi * 16]);
                rB0 = qB * w1a; rB1 = qB * w1b;
                ksumB = fmaf(wgt, SstB + qB, ksumB);
            }
            redsum2(rB0, rB1);

            if (lane == 0)
                *(float4*)&sred[ph][warp * 4] = make_float4(rA0, rA1, rB0, rB1);
            if (st == 3) CP_WAIT1();          // record t+1 landed; barrier publishes
            __syncthreads();
            const float4 f0 = *(const float4*)&sred[ph][0];
            const float4 f1 = *(const float4*)&sred[ph][4];
            const float4 f2 = *(const float4*)&sred[ph][8];
            const float4 f3 = *(const float4*)&sred[ph][12];
            const float QA0 = f0.x + f1.x + f2.x + f3.x;
            const float QA1 = f0.y + f1.y + f2.y + f3.y;
            const float QB0 = f0.z + f1.z + f2.z + f3.z;
            const float QB1 = f0.w + f1.w + f2.w + f3.w;
            ukA0 = fmaf(SstA, SW1a, QA0);  ukA1 = fmaf(SstA, SW1b, QA1);
            ukB0 = fmaf(SstB, SW1a, QB0);  ukB1 = fmaf(SstB, SW1b, QB1);
            sA0 = fmaf(wgt, ukA0, sA0);    sA1 = fmaf(wgt, ukA1, sA1);
            sB0 = fmaf(wgt, ukB0, sB0);    sB1 = fmaf(wgt, ukB1, sB1);
            ph ^= 1;
        }

        zA   = fmaf(ksumA, 1.f / 6.f, zA);
        uzA0 = fmaf(sA0,   1.f / 6.f, uzA0);
        uzA1 = fmaf(sA1,   1.f / 6.f, uzA1);
        zB   = fmaf(ksumB, 1.f / 6.f, zB);
        uzB0 = fmaf(sB0,   1.f / 6.f, uzB0);
        uzB1 = fmaf(sB1,   1.f / 6.f, uzB1);

        zrowA[(size_t)(t + 1) * Hh] = zA;
        zrowB[(size_t)(t + 1) * Hh] = zB;

        gnext += RPITCH;
        buf = (buf == 2) ? 0 : buf + 1;
    }
}

// ---------------- kernel 2: projection ----------------
__global__ __launch_bounds__(128) void proj_kernel(
    const float* __restrict__ W_out,    // (128, 4)
    const float* __restrict__ b_out,    // (4)
    float* __restrict__ out)            // (B*256, 4)
{
    __shared__ __align__(16) float zs[32][132];
    __shared__ __align__(16) float wT[4][132];
    __shared__ float bo[4];

    const int t = threadIdx.x;
    const size_t base = (size_t)blockIdx.x * 32;

#pragma unroll
    for (int j = 0; j < 4; j++) wT[j][t] = W_out[t * 4 + j];
    if (t < 4) bo[t] = b_out[t];

    const float4* zg = (const float4*)(zscr + base * Hh);
#pragma unroll
    for (int k = 0; k < 8; k++) {
        const int f4  = t + k * 128;
        const int row = f4 >> 5;
        const int c4  = f4 & 31;
        *(float4*)&zs[row][c4 * 4] = zg[f4];
    }
    __syncthreads();

    const int row = t >> 2, o = t & 3;
    float acc[4] = {0.f, 0.f, 0.f, 0.f};
#pragma unroll
    for (int i = 0; i < 8; i++) {
#pragma unroll
        for (int j = 0; j < 4; j++) {
            const float4 zv = *(const float4*)&zs[row][(i * 4 + j) * 4];
            const float4 wv = *(const float4*)&wT[o][(i * 4 + j) * 4];
            acc[j] = fmaf(zv.x, wv.x, acc[j]);
            acc[j] = fmaf(zv.y, wv.y, acc[j]);
            acc[j] = fmaf(zv.z, wv.z, acc[j]);
            acc[j] = fmaf(zv.w, wv.w, acc[j]);
        }
    }
    out[base * 4 + t] = (acc[0] + acc[1]) + (acc[2] + acc[3]) + bo[o];
}

extern "C" void kernel_launch(void* const* d_in, const int* in_sizes, int n_in,
                              void* d_out, int out_size) {
    const float* coeffs = (const float*)d_in[0];
    const float* W_init = (const float*)d_in[1];
    const float* b_init = (const float*)d_in[2];
    const float* W1     = (const float*)d_in[3];
    const float* b1     = (const float*)d_in[4];
    const float* W2     = (const float*)d_in[5];
    const float* b2     = (const float*)d_in[6];
    const float* W_out  = (const float*)d_in[7];
    const float* b_out  = (const float*)d_in[8];
    float* out = (float*)d_out;

    prep_kernel<<<(4096 * 255) / 256, 256>>>(coeffs);          // 4080 blocks
    ncde_kernel<<<2048, 128>>>(coeffs, W_init, b_init, W1, b1, W2, b2);
    proj_kernel<<<(4096 * 256) / 32, 128>>>(W_out, b_out, out);
}